// round 3
// baseline (speedup 1.0000x reference)
#include <cuda_runtime.h>
#include <math.h>

#define NTOK 4096
#define DIM 1024
#define NHEADS 16
#define HD 64
#define QKV_N 3072
#define SCALE 0.125f   // 1/sqrt(64)

// ---------------- scratch (no allocations allowed) ----------------
__device__ float g_qkv[NTOK * QKV_N];          // 48 MB
__device__ float g_Q[NHEADS * NTOK * HD];      // 16 MB
__device__ float g_K[NHEADS * NTOK * HD];      // 16 MB
__device__ float g_V[NHEADS * NTOK * HD];      // 16 MB
__device__ float g_attn[NTOK * DIM];           // 16 MB

// ---------------- generic tiled GEMM: C = A(MxK) @ B(KxN) + bias ----------------
#define BM 128
#define BN 128
#define BK 16
#define TM 8
#define TN 8

__global__ __launch_bounds__(256) void gemm_bias_kernel(
    const float* __restrict__ A, const float* __restrict__ B,
    const float* __restrict__ bias, float* __restrict__ C,
    int M, int N, int K)
{
    __shared__ float As[BK][BM];
    __shared__ float Bs[BK][BN];

    const int tx = threadIdx.x % 16;
    const int ty = threadIdx.x / 16;
    const int rowBase = blockIdx.y * BM;
    const int colBase = blockIdx.x * BN;

    float acc[TM][TN];
    #pragma unroll
    for (int i = 0; i < TM; i++)
        #pragma unroll
        for (int j = 0; j < TN; j++) acc[i][j] = 0.f;

    for (int k0 = 0; k0 < K; k0 += BK) {
        // A tile: 128 rows x 16 cols = 512 float4, 2 per thread (transposed store)
        #pragma unroll
        for (int i = 0; i < 2; i++) {
            int v = threadIdx.x + i * 256;       // float4 idx
            int r = v >> 2;                       // 4 float4 per row of 16
            int c = (v & 3) * 4;
            float4 f = *(const float4*)&A[(size_t)(rowBase + r) * K + k0 + c];
            As[c + 0][r] = f.x; As[c + 1][r] = f.y;
            As[c + 2][r] = f.z; As[c + 3][r] = f.w;
        }
        // B tile: 16 rows x 128 cols = 512 float4, direct store
        #pragma unroll
        for (int i = 0; i < 2; i++) {
            int v = threadIdx.x + i * 256;
            int r = v >> 5;                       // 32 float4 per row of 128
            int c = (v & 31) * 4;
            *(float4*)&Bs[r][c] = *(const float4*)&B[(size_t)(k0 + r) * N + colBase + c];
        }
        __syncthreads();

        #pragma unroll
        for (int k = 0; k < BK; k++) {
            float a[TM], b[TN];
            #pragma unroll
            for (int i = 0; i < TM; i++) a[i] = As[k][ty * TM + i];
            #pragma unroll
            for (int j = 0; j < TN; j++) b[j] = Bs[k][tx * TN + j];
            #pragma unroll
            for (int i = 0; i < TM; i++)
                #pragma unroll
                for (int j = 0; j < TN; j++)
                    acc[i][j] += a[i] * b[j];
        }
        __syncthreads();
    }

    #pragma unroll
    for (int i = 0; i < TM; i++) {
        int r = rowBase + ty * TM + i;
        #pragma unroll
        for (int j = 0; j < TN; j += 4) {
            int c = colBase + tx * TN + j;
            float4 o;
            o.x = acc[i][j + 0] + bias[c + 0];
            o.y = acc[i][j + 1] + bias[c + 1];
            o.z = acc[i][j + 2] + bias[c + 2];
            o.w = acc[i][j + 3] + bias[c + 3];
            *(float4*)&C[(size_t)r * N + c] = o;
        }
    }
}

// ---------------- RoPE + split qkv -> Q/K/V in [h][n][hd] ----------------
__global__ void rope_split_kernel(const float* __restrict__ cosb,
                                  const float* __restrict__ sinb)
{
    int idx = blockIdx.x * blockDim.x + threadIdx.x;   // over NTOK*NHEADS*32
    if (idx >= NTOK * NHEADS * 32) return;
    int d = idx & 31;
    int h = (idx >> 5) & 15;
    int n = idx >> 9;

    const float* base = g_qkv + (size_t)n * QKV_N;
    float c = cosb[n * 32 + d];
    float s = sinb[n * 32 + d];

    size_t ho = ((size_t)h * NTOK + n) * HD;

    float x1 = base[h * HD + d];
    float x2 = base[h * HD + d + 32];
    g_Q[ho + d]      = x1 * c - x2 * s;
    g_Q[ho + d + 32] = x2 * c + x1 * s;

    float y1 = base[DIM + h * HD + d];
    float y2 = base[DIM + h * HD + d + 32];
    g_K[ho + d]      = y1 * c - y2 * s;
    g_K[ho + d + 32] = y2 * c + y1 * s;

    g_V[ho + d]      = base[2 * DIM + h * HD + d];
    g_V[ho + d + 32] = base[2 * DIM + h * HD + d + 32];
}

// ---------------- flash attention: 1 thread = 1 query row ----------------
#define BMQ 128
#define BNK 16

__global__ __launch_bounds__(BMQ) void attn_kernel()
{
    const int h = blockIdx.y;
    const int qrow = blockIdx.x * BMQ + threadIdx.x;

    const float* qp = g_Q + ((size_t)h * NTOK + qrow) * HD;
    float q[HD];
    #pragma unroll
    for (int d = 0; d < HD; d += 4) {
        float4 f = *(const float4*)&qp[d];
        q[d] = f.x; q[d + 1] = f.y; q[d + 2] = f.z; q[d + 3] = f.w;
    }

    float m = -INFINITY, l = 0.f;
    float acc[HD];
    #pragma unroll
    for (int d = 0; d < HD; d++) acc[d] = 0.f;

    __shared__ float Ks[BNK][HD];
    __shared__ float Vs[BNK][HD];

    const float* kbase = g_K + (size_t)h * NTOK * HD;
    const float* vbase = g_V + (size_t)h * NTOK * HD;

    for (int t = 0; t < NTOK; t += BNK) {
        // cooperative load: 16x64 floats each = 256 float4, 2 per thread per matrix
        #pragma unroll
        for (int i = 0; i < 2; i++) {
            int v = threadIdx.x + i * BMQ;   // 0..255
            int r = v >> 4;
            int c = (v & 15) * 4;
            *(float4*)&Ks[r][c] = *(const float4*)&kbase[(size_t)(t + r) * HD + c];
            *(float4*)&Vs[r][c] = *(const float4*)&vbase[(size_t)(t + r) * HD + c];
        }
        __syncthreads();

        float s[BNK];
        #pragma unroll
        for (int j = 0; j < BNK; j++) {
            float d0 = 0.f;
            #pragma unroll
            for (int d = 0; d < HD; d += 4) {
                float4 kk = *(const float4*)&Ks[j][d];
                d0 += q[d] * kk.x + q[d + 1] * kk.y + q[d + 2] * kk.z + q[d + 3] * kk.w;
            }
            s[j] = d0 * SCALE;
        }

        float mt = m;
        #pragma unroll
        for (int j = 0; j < BNK; j++) mt = fmaxf(mt, s[j]);
        float corr = __expf(m - mt);
        m = mt;
        l *= corr;
        #pragma unroll
        for (int d = 0; d < HD; d++) acc[d] *= corr;

        #pragma unroll
        for (int j = 0; j < BNK; j++) {
            float p = __expf(s[j] - m);
            l += p;
            #pragma unroll
            for (int d = 0; d < HD; d += 4) {
                float4 vv = *(const float4*)&Vs[j][d];
                acc[d]     += p * vv.x;
                acc[d + 1] += p * vv.y;
                acc[d + 2] += p * vv.z;
                acc[d + 3] += p * vv.w;
            }
        }
        __syncthreads();
    }

    float inv = 1.f / l;
    float* op = g_attn + (size_t)qrow * DIM + h * HD;
    #pragma unroll
    for (int d = 0; d < HD; d += 4) {
        float4 o;
        o.x = acc[d] * inv;     o.y = acc[d + 1] * inv;
        o.z = acc[d + 2] * inv; o.w = acc[d + 3] * inv;
        *(float4*)&op[d] = o;
    }
}

// ---------------- launch ----------------
extern "C" void kernel_launch(void* const* d_in, const int* in_sizes, int n_in,
                              void* d_out, int out_size)
{
    const float* x      = (const float*)d_in[0];   // [1,4096,1024]
    const float* cosb   = (const float*)d_in[1];   // [1,4096,32]
    const float* sinb   = (const float*)d_in[2];   // [1,4096,32]
    const float* w_qkv  = (const float*)d_in[3];   // [1024,3072]
    const float* b_qkv  = (const float*)d_in[4];   // [3072]
    const float* w_proj = (const float*)d_in[5];   // [1024,1024]
    const float* b_proj = (const float*)d_in[6];   // [1024]
    float* out = (float*)d_out;

    float *p_qkv, *p_attn;
    cudaGetSymbolAddress((void**)&p_qkv, g_qkv);
    cudaGetSymbolAddress((void**)&p_attn, g_attn);

    // 1) QKV GEMM: [4096,1024] @ [1024,3072] + b
    {
        dim3 grid(QKV_N / BN, NTOK / BM);
        gemm_bias_kernel<<<grid, 256>>>(x, w_qkv, b_qkv, p_qkv, NTOK, QKV_N, DIM);
    }
    // 2) RoPE + split into [h][n][hd]
    {
        int total = NTOK * NHEADS * 32;
        rope_split_kernel<<<(total + 255) / 256, 256>>>(cosb, sinb);
    }
    // 3) attention
    {
        dim3 grid(NTOK / BMQ, NHEADS);
        attn_kernel<<<grid, BMQ>>>();
    }
    // 4) proj GEMM: [4096,1024] @ [1024,1024] + b -> out
    {
        dim3 grid(DIM / BN, NTOK / BM);
        gemm_bias_kernel<<<grid, 256>>>(p_attn, w_proj, b_proj, out, NTOK, DIM, DIM);
    }
}

// round 6
// speedup vs baseline: 2.5917x; 2.5917x over previous
#include <cuda_runtime.h>
#include <stdint.h>
#include <math.h>

#define NTOK 4096
#define DIM 1024
#define NHEADS 16
#define HD 64
#define QKV_N 3072
#define SCALE 0.125f   // 1/sqrt(64)

// ---------------- scratch (no allocations allowed) ----------------
__device__ float g_qkv[NTOK * QKV_N];          // 48 MB
__device__ float g_Q[NHEADS * NTOK * HD];      // 16 MB
__device__ float g_K[NHEADS * NTOK * HD];      // 16 MB
__device__ float g_V[NHEADS * NTOK * HD];      // 16 MB
__device__ float g_attn[NTOK * DIM];           // 16 MB

// ---------------- generic tiled GEMM: C = A(MxK) @ B(KxN) + bias ----------------
#define BM 128
#define BN 128
#define BK 16
#define TM 8
#define TN 8

__global__ __launch_bounds__(256) void gemm_bias_kernel(
    const float* __restrict__ A, const float* __restrict__ B,
    const float* __restrict__ bias, float* __restrict__ C,
    int M, int N, int K)
{
    __shared__ float As[BK][BM];
    __shared__ float Bs[BK][BN];

    const int tx = threadIdx.x % 16;
    const int ty = threadIdx.x / 16;
    const int rowBase = blockIdx.y * BM;
    const int colBase = blockIdx.x * BN;

    float acc[TM][TN];
    #pragma unroll
    for (int i = 0; i < TM; i++)
        #pragma unroll
        for (int j = 0; j < TN; j++) acc[i][j] = 0.f;

    for (int k0 = 0; k0 < K; k0 += BK) {
        #pragma unroll
        for (int i = 0; i < 2; i++) {
            int v = threadIdx.x + i * 256;
            int r = v >> 2;
            int c = (v & 3) * 4;
            float4 f = *(const float4*)&A[(size_t)(rowBase + r) * K + k0 + c];
            As[c + 0][r] = f.x; As[c + 1][r] = f.y;
            As[c + 2][r] = f.z; As[c + 3][r] = f.w;
        }
        #pragma unroll
        for (int i = 0; i < 2; i++) {
            int v = threadIdx.x + i * 256;
            int r = v >> 5;
            int c = (v & 31) * 4;
            *(float4*)&Bs[r][c] = *(const float4*)&B[(size_t)(k0 + r) * N + colBase + c];
        }
        __syncthreads();

        #pragma unroll
        for (int k = 0; k < BK; k++) {
            float a[TM], b[TN];
            #pragma unroll
            for (int i = 0; i < TM; i++) a[i] = As[k][ty * TM + i];
            #pragma unroll
            for (int j = 0; j < TN; j++) b[j] = Bs[k][tx * TN + j];
            #pragma unroll
            for (int i = 0; i < TM; i++)
                #pragma unroll
                for (int j = 0; j < TN; j++)
                    acc[i][j] += a[i] * b[j];
        }
        __syncthreads();
    }

    #pragma unroll
    for (int i = 0; i < TM; i++) {
        int r = rowBase + ty * TM + i;
        #pragma unroll
        for (int j = 0; j < TN; j += 4) {
            int c = colBase + tx * TN + j;
            float4 o;
            o.x = acc[i][j + 0] + bias[c + 0];
            o.y = acc[i][j + 1] + bias[c + 1];
            o.z = acc[i][j + 2] + bias[c + 2];
            o.w = acc[i][j + 3] + bias[c + 3];
            *(float4*)&C[(size_t)r * N + c] = o;
        }
    }
}

// ---------------- RoPE + split qkv -> Q/K/V in [h][n][hd] ----------------
__global__ void rope_split_kernel(const float* __restrict__ cosb,
                                  const float* __restrict__ sinb)
{
    int idx = blockIdx.x * blockDim.x + threadIdx.x;
    if (idx >= NTOK * NHEADS * 32) return;
    int d = idx & 31;
    int h = (idx >> 5) & 15;
    int n = idx >> 9;

    const float* base = g_qkv + (size_t)n * QKV_N;
    float c = cosb[n * 32 + d];
    float s = sinb[n * 32 + d];

    size_t ho = ((size_t)h * NTOK + n) * HD;

    float x1 = base[h * HD + d];
    float x2 = base[h * HD + d + 32];
    g_Q[ho + d]      = x1 * c - x2 * s;
    g_Q[ho + d + 32] = x2 * c + x1 * s;

    float y1 = base[DIM + h * HD + d];
    float y2 = base[DIM + h * HD + d + 32];
    g_K[ho + d]      = y1 * c - y2 * s;
    g_K[ho + d + 32] = y2 * c + y1 * s;

    g_V[ho + d]      = base[2 * DIM + h * HD + d];
    g_V[ho + d + 32] = base[2 * DIM + h * HD + d + 32];
}

// ---------------- flash attention with mma.sync tf32 ----------------
// CTA: 64 queries x 1 head. 4 warps, each owns m16 query rows.
// S = Q K^T via m16n8k8 tf32; online softmax on fragments; P through smem
// (reusing the K buffer) back to A-fragments; O += P V via m16n8k8 tf32.

#define ATT_BQ 64
#define ATT_BK 64
#define KST 68   // padded stride (floats)

__device__ __forceinline__ uint32_t cvt_tf32(float x) {
    uint32_t r;
    asm("cvt.rna.tf32.f32 %0, %1;" : "=r"(r) : "f"(x));
    return r;
}

__device__ __forceinline__ void mma_tf32(float& c0, float& c1, float& c2, float& c3,
                                         uint32_t a0, uint32_t a1, uint32_t a2, uint32_t a3,
                                         uint32_t b0, uint32_t b1) {
    asm volatile(
        "mma.sync.aligned.m16n8k8.row.col.f32.tf32.tf32.f32 "
        "{%0,%1,%2,%3}, {%4,%5,%6,%7}, {%8,%9}, {%0,%1,%2,%3};"
        : "+f"(c0), "+f"(c1), "+f"(c2), "+f"(c3)
        : "r"(a0), "r"(a1), "r"(a2), "r"(a3), "r"(b0), "r"(b1));
}

__global__ __launch_bounds__(128) void attn_mma_kernel()
{
    const int h = blockIdx.y;
    const int q0 = blockIdx.x * ATT_BQ;
    const int wid = threadIdx.x >> 5;
    const int lane = threadIdx.x & 31;
    const int qr = lane >> 2;   // groupID 0..7
    const int qc = lane & 3;    // thread-in-group 0..3

    // Ks is reused as the P buffer after S is computed (barrier in between).
    __shared__ float Ks[ATT_BK][KST];
    __shared__ float Vs[ATT_BK][KST];

    // ---- load Q fragments for this warp's 16 rows (pre-scaled, tf32) ----
    const float* qbase = g_Q + ((size_t)h * NTOK + q0 + wid * 16) * HD;
    uint32_t qf[8][4];
    #pragma unroll
    for (int kk = 0; kk < 8; kk++) {
        qf[kk][0] = cvt_tf32(qbase[(size_t)(qr)     * HD + kk * 8 + qc]     * SCALE);
        qf[kk][1] = cvt_tf32(qbase[(size_t)(qr + 8) * HD + kk * 8 + qc]     * SCALE);
        qf[kk][2] = cvt_tf32(qbase[(size_t)(qr)     * HD + kk * 8 + qc + 4] * SCALE);
        qf[kk][3] = cvt_tf32(qbase[(size_t)(qr + 8) * HD + kk * 8 + qc + 4] * SCALE);
    }

    float m0 = -1e30f, m1 = -1e30f, l0 = 0.f, l1 = 0.f;
    float o[8][4];
    #pragma unroll
    for (int nb = 0; nb < 8; nb++)
        #pragma unroll
        for (int r = 0; r < 4; r++) o[nb][r] = 0.f;

    const float* kb = g_K + (size_t)h * NTOK * HD;
    const float* vb = g_V + (size_t)h * NTOK * HD;

    #pragma unroll 1
    for (int t = 0; t < NTOK; t += ATT_BK) {
        // ---- cooperative K/V tile load: 64x64 each, 8 float4 per thread ----
        #pragma unroll
        for (int i = 0; i < 8; i++) {
            int v = threadIdx.x + i * 128;
            int r = v >> 4;
            int c = (v & 15) * 4;
            *(float4*)&Ks[r][c] = *(const float4*)&kb[(size_t)(t + r) * HD + c];
            *(float4*)&Vs[r][c] = *(const float4*)&vb[(size_t)(t + r) * HD + c];
        }
        __syncthreads();

        // ---- S = Q K^T  (16 x 64 per warp) ----
        float sfr[8][4];
        #pragma unroll
        for (int nb = 0; nb < 8; nb++)
            #pragma unroll
            for (int r = 0; r < 4; r++) sfr[nb][r] = 0.f;

        #pragma unroll
        for (int kk = 0; kk < 8; kk++) {
            #pragma unroll
            for (int nb = 0; nb < 8; nb++) {
                uint32_t b0 = cvt_tf32(Ks[nb * 8 + qr][kk * 8 + qc]);
                uint32_t b1 = cvt_tf32(Ks[nb * 8 + qr][kk * 8 + qc + 4]);
                mma_tf32(sfr[nb][0], sfr[nb][1], sfr[nb][2], sfr[nb][3],
                         qf[kk][0], qf[kk][1], qf[kk][2], qf[kk][3], b0, b1);
            }
        }
        __syncthreads();   // all warps done reading Ks -> safe to overwrite with P

        // ---- online softmax on fragments ----
        float mt0 = m0, mt1 = m1;
        #pragma unroll
        for (int nb = 0; nb < 8; nb++) {
            mt0 = fmaxf(mt0, fmaxf(sfr[nb][0], sfr[nb][1]));
            mt1 = fmaxf(mt1, fmaxf(sfr[nb][2], sfr[nb][3]));
        }
        mt0 = fmaxf(mt0, __shfl_xor_sync(0xffffffff, mt0, 1));
        mt0 = fmaxf(mt0, __shfl_xor_sync(0xffffffff, mt0, 2));
        mt1 = fmaxf(mt1, __shfl_xor_sync(0xffffffff, mt1, 1));
        mt1 = fmaxf(mt1, __shfl_xor_sync(0xffffffff, mt1, 2));

        float c0 = __expf(m0 - mt0);
        float c1 = __expf(m1 - mt1);
        m0 = mt0; m1 = mt1;
        l0 *= c0; l1 *= c1;
        #pragma unroll
        for (int nb = 0; nb < 8; nb++) {
            o[nb][0] *= c0; o[nb][1] *= c0;
            o[nb][2] *= c1; o[nb][3] *= c1;
        }

        // ---- P = exp(S - m), tf32-converted, into smem (Ks buffer) ----
        #pragma unroll
        for (int nb = 0; nb < 8; nb++) {
            float p0 = __expf(sfr[nb][0] - m0);
            float p1 = __expf(sfr[nb][1] - m0);
            float p2 = __expf(sfr[nb][2] - m1);
            float p3 = __expf(sfr[nb][3] - m1);
            l0 += p0 + p1;
            l1 += p2 + p3;
            float2 w0, w1;
            w0.x = __uint_as_float(cvt_tf32(p0));
            w0.y = __uint_as_float(cvt_tf32(p1));
            w1.x = __uint_as_float(cvt_tf32(p2));
            w1.y = __uint_as_float(cvt_tf32(p3));
            *(float2*)&Ks[wid * 16 + qr]    [nb * 8 + 2 * qc] = w0;
            *(float2*)&Ks[wid * 16 + qr + 8][nb * 8 + 2 * qc] = w1;
        }
        __syncwarp();

        // ---- O += P V ----
        #pragma unroll
        for (int kk = 0; kk < 8; kk++) {
            uint32_t a0 = __float_as_uint(Ks[wid * 16 + qr]    [kk * 8 + qc]);
            uint32_t a1 = __float_as_uint(Ks[wid * 16 + qr + 8][kk * 8 + qc]);
            uint32_t a2 = __float_as_uint(Ks[wid * 16 + qr]    [kk * 8 + qc + 4]);
            uint32_t a3 = __float_as_uint(Ks[wid * 16 + qr + 8][kk * 8 + qc + 4]);
            #pragma unroll
            for (int nb = 0; nb < 8; nb++) {
                uint32_t b0 = cvt_tf32(Vs[kk * 8 + qc]    [nb * 8 + qr]);
                uint32_t b1 = cvt_tf32(Vs[kk * 8 + qc + 4][nb * 8 + qr]);
                mma_tf32(o[nb][0], o[nb][1], o[nb][2], o[nb][3],
                         a0, a1, a2, a3, b0, b1);
            }
        }
        __syncthreads();   // P/V reads done before next tile's overwrite
    }

    // ---- finalize ----
    l0 += __shfl_xor_sync(0xffffffff, l0, 1);
    l0 += __shfl_xor_sync(0xffffffff, l0, 2);
    l1 += __shfl_xor_sync(0xffffffff, l1, 1);
    l1 += __shfl_xor_sync(0xffffffff, l1, 2);
    float inv0 = 1.f / l0;
    float inv1 = 1.f / l1;

    int row0 = q0 + wid * 16 + qr;
    #pragma unroll
    for (int nb = 0; nb < 8; nb++) {
        int col = h * HD + nb * 8 + 2 * qc;
        float2 w0, w1;
        w0.x = o[nb][0] * inv0; w0.y = o[nb][1] * inv0;
        w1.x = o[nb][2] * inv1; w1.y = o[nb][3] * inv1;
        *(float2*)&g_attn[(size_t)row0 * DIM + col] = w0;
        *(float2*)&g_attn[(size_t)(row0 + 8) * DIM + col] = w1;
    }
}

// ---------------- launch ----------------
extern "C" void kernel_launch(void* const* d_in, const int* in_sizes, int n_in,
                              void* d_out, int out_size)
{
    const float* x      = (const float*)d_in[0];
    const float* cosb   = (const float*)d_in[1];
    const float* sinb   = (const float*)d_in[2];
    const float* w_qkv  = (const float*)d_in[3];
    const float* b_qkv  = (const float*)d_in[4];
    const float* w_proj = (const float*)d_in[5];
    const float* b_proj = (const float*)d_in[6];
    float* out = (float*)d_out;

    float *p_qkv, *p_attn;
    cudaGetSymbolAddress((void**)&p_qkv, g_qkv);
    cudaGetSymbolAddress((void**)&p_attn, g_attn);

    // 1) QKV GEMM
    {
        dim3 grid(QKV_N / BN, NTOK / BM);
        gemm_bias_kernel<<<grid, 256>>>(x, w_qkv, b_qkv, p_qkv, NTOK, QKV_N, DIM);
    }
    // 2) RoPE + split
    {
        int total = NTOK * NHEADS * 32;
        rope_split_kernel<<<(total + 255) / 256, 256>>>(cosb, sinb);
    }
    // 3) attention (tensor-core tf32)
    {
        dim3 grid(NTOK / ATT_BQ, NHEADS);
        attn_mma_kernel<<<grid, 128>>>();
    }
    // 4) proj GEMM
    {
        dim3 grid(DIM / BN, NTOK / BM);
        gemm_bias_kernel<<<grid, 256>>>(p_attn, w_proj, b_proj, out, NTOK, DIM, DIM);
    }
}

// round 7
// speedup vs baseline: 3.7736x; 1.4560x over previous
#include <cuda_runtime.h>
#include <stdint.h>
#include <math.h>

#define NTOK 4096
#define DIM 1024
#define NHEADS 16
#define HD 64
#define QKV_N 3072
#define SCALE 0.125f   // 1/sqrt(64)

// ---------------- scratch (no allocations allowed) ----------------
__device__ float g_qkv[NTOK * QKV_N];
__device__ float g_Q[NHEADS * NTOK * HD];
__device__ float g_K[NHEADS * NTOK * HD];
__device__ float g_V[NHEADS * NTOK * HD];
__device__ float g_attn[NTOK * DIM];

__device__ __forceinline__ uint32_t cvt_tf32(float x) {
    uint32_t r;
    asm("cvt.rna.tf32.f32 %0, %1;" : "=r"(r) : "f"(x));
    return r;
}

__device__ __forceinline__ void mma_tf32(float& c0, float& c1, float& c2, float& c3,
                                         uint32_t a0, uint32_t a1, uint32_t a2, uint32_t a3,
                                         uint32_t b0, uint32_t b1) {
    asm volatile(
        "mma.sync.aligned.m16n8k8.row.col.f32.tf32.tf32.f32 "
        "{%0,%1,%2,%3}, {%4,%5,%6,%7}, {%8,%9}, {%0,%1,%2,%3};"
        : "+f"(c0), "+f"(c1), "+f"(c2), "+f"(c3)
        : "r"(a0), "r"(a1), "r"(a2), "r"(a3), "r"(b0), "r"(b1));
}

// ---------------- tf32 MMA GEMM: C = A(MxK) @ B(KxN) + bias ----------------
// 128x128 CTA tile, BK=16, 256 threads = 8 warps in 2(m) x 4(n), warp tile 64x32.
#define GBM 128
#define GBN 128
#define GBK 16
#define GST 136   // smem row stride (floats): 136 mod 32 = 8 -> conflict-free frags

__global__ __launch_bounds__(256) void gemm_tf32_kernel(
    const float* __restrict__ A, const float* __restrict__ B,
    const float* __restrict__ bias, float* __restrict__ C,
    int M, int N, int K)
{
    __shared__ float Ast[GBK][GST];   // A^T tile: [k][m], tf32 bits
    __shared__ float Bs[GBK][GST];    // B tile:  [k][n], tf32 bits

    const int tid = threadIdx.x;
    const int wid = tid >> 5;
    const int lane = tid & 31;
    const int qr = lane >> 2;
    const int qc = lane & 3;
    const int wm = wid >> 2;          // 0..1
    const int wn = wid & 3;           // 0..3
    const int rowBase = blockIdx.y * GBM;
    const int colBase = blockIdx.x * GBN;

    float acc[4][4][4];
    #pragma unroll
    for (int mi = 0; mi < 4; mi++)
        #pragma unroll
        for (int ni = 0; ni < 4; ni++)
            #pragma unroll
            for (int r = 0; r < 4; r++) acc[mi][ni][r] = 0.f;

    for (int k0 = 0; k0 < K; k0 += GBK) {
        // A tile: 128 rows x 16 k -> transposed scatter (tf32 bits)
        #pragma unroll
        for (int i = 0; i < 2; i++) {
            int v = tid + i * 256;        // 0..511
            int r = v >> 2;                // row 0..127
            int c = (v & 3) * 4;           // k 0,4,8,12
            float4 f = *(const float4*)&A[(size_t)(rowBase + r) * K + k0 + c];
            Ast[c + 0][r] = __uint_as_float(cvt_tf32(f.x));
            Ast[c + 1][r] = __uint_as_float(cvt_tf32(f.y));
            Ast[c + 2][r] = __uint_as_float(cvt_tf32(f.z));
            Ast[c + 3][r] = __uint_as_float(cvt_tf32(f.w));
        }
        // B tile: 16 k x 128 n -> direct (tf32 bits)
        #pragma unroll
        for (int i = 0; i < 2; i++) {
            int v = tid + i * 256;
            int r = v >> 5;                // k 0..15
            int c = (v & 31) * 4;          // n
            float4 f = *(const float4*)&B[(size_t)(k0 + r) * N + colBase + c];
            float4 g;
            g.x = __uint_as_float(cvt_tf32(f.x));
            g.y = __uint_as_float(cvt_tf32(f.y));
            g.z = __uint_as_float(cvt_tf32(f.z));
            g.w = __uint_as_float(cvt_tf32(f.w));
            *(float4*)&Bs[r][c] = g;
        }
        __syncthreads();

        #pragma unroll
        for (int kk = 0; kk < 2; kk++) {
            uint32_t af[4][4], bf[4][2];
            #pragma unroll
            for (int mi = 0; mi < 4; mi++) {
                int m = wm * 64 + mi * 16;
                af[mi][0] = __float_as_uint(Ast[kk * 8 + qc]    [m + qr]);
                af[mi][1] = __float_as_uint(Ast[kk * 8 + qc]    [m + qr + 8]);
                af[mi][2] = __float_as_uint(Ast[kk * 8 + qc + 4][m + qr]);
                af[mi][3] = __float_as_uint(Ast[kk * 8 + qc + 4][m + qr + 8]);
            }
            #pragma unroll
            for (int ni = 0; ni < 4; ni++) {
                int n = wn * 32 + ni * 8;
                bf[ni][0] = __float_as_uint(Bs[kk * 8 + qc]    [n + qr]);
                bf[ni][1] = __float_as_uint(Bs[kk * 8 + qc + 4][n + qr]);
            }
            #pragma unroll
            for (int mi = 0; mi < 4; mi++)
                #pragma unroll
                for (int ni = 0; ni < 4; ni++)
                    mma_tf32(acc[mi][ni][0], acc[mi][ni][1], acc[mi][ni][2], acc[mi][ni][3],
                             af[mi][0], af[mi][1], af[mi][2], af[mi][3],
                             bf[ni][0], bf[ni][1]);
        }
        __syncthreads();
    }

    // epilogue: C-frag (qr, 2qc),(qr,2qc+1) / (qr+8, ...)
    #pragma unroll
    for (int mi = 0; mi < 4; mi++) {
        int m = rowBase + wm * 64 + mi * 16;
        #pragma unroll
        for (int ni = 0; ni < 4; ni++) {
            int n = colBase + wn * 32 + ni * 8 + 2 * qc;
            float bx = bias[n], by = bias[n + 1];
            float2 w0, w1;
            w0.x = acc[mi][ni][0] + bx;  w0.y = acc[mi][ni][1] + by;
            w1.x = acc[mi][ni][2] + bx;  w1.y = acc[mi][ni][3] + by;
            *(float2*)&C[(size_t)(m + qr) * N + n] = w0;
            *(float2*)&C[(size_t)(m + qr + 8) * N + n] = w1;
        }
    }
}

// ---------------- RoPE + split qkv -> Q/K/V in [h][n][hd] ----------------
__global__ void rope_split_kernel(const float* __restrict__ cosb,
                                  const float* __restrict__ sinb)
{
    int idx = blockIdx.x * blockDim.x + threadIdx.x;
    if (idx >= NTOK * NHEADS * 32) return;
    int d = idx & 31;
    int h = (idx >> 5) & 15;
    int n = idx >> 9;

    const float* base = g_qkv + (size_t)n * QKV_N;
    float c = cosb[n * 32 + d];
    float s = sinb[n * 32 + d];

    size_t ho = ((size_t)h * NTOK + n) * HD;

    float x1 = base[h * HD + d];
    float x2 = base[h * HD + d + 32];
    g_Q[ho + d]      = x1 * c - x2 * s;
    g_Q[ho + d + 32] = x2 * c + x1 * s;

    float y1 = base[DIM + h * HD + d];
    float y2 = base[DIM + h * HD + d + 32];
    g_K[ho + d]      = y1 * c - y2 * s;
    g_K[ho + d + 32] = y2 * c + y1 * s;

    g_V[ho + d]      = base[2 * DIM + h * HD + d];
    g_V[ho + d + 32] = base[2 * DIM + h * HD + d + 32];
}

// ---------------- flash attention with mma.sync tf32 ----------------
// CTA: 128 queries x 1 head, 8 warps (16 q-rows each). K/V tiles pre-converted
// to tf32 at load. P in its own smem region (dynamic smem: Ks + Vs + Ps).
#define ATT_BQ 128
#define ATT_BK 64
#define KST 68    // padded row stride (floats)

__global__ __launch_bounds__(256) void attn_mma_kernel()
{
    extern __shared__ float sm[];
    float (*Ks)[KST] = (float(*)[KST])sm;                       // [64][68] tf32 bits
    float (*Vs)[KST] = (float(*)[KST])(sm + ATT_BK * KST);      // [64][68] tf32 bits
    float (*Ps)[KST] = (float(*)[KST])(sm + 2 * ATT_BK * KST);  // [128][68] tf32 bits

    const int h = blockIdx.y;
    const int q0 = blockIdx.x * ATT_BQ;
    const int wid = threadIdx.x >> 5;
    const int lane = threadIdx.x & 31;
    const int qr = lane >> 2;
    const int qc = lane & 3;

    // ---- Q fragments (pre-scaled, tf32) ----
    const float* qbase = g_Q + ((size_t)h * NTOK + q0 + wid * 16) * HD;
    uint32_t qf[8][4];
    #pragma unroll
    for (int kk = 0; kk < 8; kk++) {
        qf[kk][0] = cvt_tf32(qbase[(size_t)(qr)     * HD + kk * 8 + qc]     * SCALE);
        qf[kk][1] = cvt_tf32(qbase[(size_t)(qr + 8) * HD + kk * 8 + qc]     * SCALE);
        qf[kk][2] = cvt_tf32(qbase[(size_t)(qr)     * HD + kk * 8 + qc + 4] * SCALE);
        qf[kk][3] = cvt_tf32(qbase[(size_t)(qr + 8) * HD + kk * 8 + qc + 4] * SCALE);
    }

    float m0 = -1e30f, m1 = -1e30f, l0 = 0.f, l1 = 0.f;
    float o[8][4];
    #pragma unroll
    for (int nb = 0; nb < 8; nb++)
        #pragma unroll
        for (int r = 0; r < 4; r++) o[nb][r] = 0.f;

    const float* kb = g_K + (size_t)h * NTOK * HD;
    const float* vb = g_V + (size_t)h * NTOK * HD;

    #pragma unroll 1
    for (int t = 0; t < NTOK; t += ATT_BK) {
        // ---- K/V tile load + tf32 convert: 64x64 each, 4 float4/thread ----
        #pragma unroll
        for (int i = 0; i < 4; i++) {
            int v = threadIdx.x + i * 256;
            int r = v >> 4;
            int c = (v & 15) * 4;
            float4 fk = *(const float4*)&kb[(size_t)(t + r) * HD + c];
            float4 fv = *(const float4*)&vb[(size_t)(t + r) * HD + c];
            float4 gk, gv;
            gk.x = __uint_as_float(cvt_tf32(fk.x)); gk.y = __uint_as_float(cvt_tf32(fk.y));
            gk.z = __uint_as_float(cvt_tf32(fk.z)); gk.w = __uint_as_float(cvt_tf32(fk.w));
            gv.x = __uint_as_float(cvt_tf32(fv.x)); gv.y = __uint_as_float(cvt_tf32(fv.y));
            gv.z = __uint_as_float(cvt_tf32(fv.z)); gv.w = __uint_as_float(cvt_tf32(fv.w));
            *(float4*)&Ks[r][c] = gk;
            *(float4*)&Vs[r][c] = gv;
        }
        __syncthreads();

        // ---- S = Q K^T (16 x 64 per warp) ----
        float sfr[8][4];
        #pragma unroll
        for (int nb = 0; nb < 8; nb++)
            #pragma unroll
            for (int r = 0; r < 4; r++) sfr[nb][r] = 0.f;

        #pragma unroll
        for (int kk = 0; kk < 8; kk++) {
            #pragma unroll
            for (int nb = 0; nb < 8; nb++) {
                uint32_t b0 = __float_as_uint(Ks[nb * 8 + qr][kk * 8 + qc]);
                uint32_t b1 = __float_as_uint(Ks[nb * 8 + qr][kk * 8 + qc + 4]);
                mma_tf32(sfr[nb][0], sfr[nb][1], sfr[nb][2], sfr[nb][3],
                         qf[kk][0], qf[kk][1], qf[kk][2], qf[kk][3], b0, b1);
            }
        }

        // ---- online softmax ----
        float mt0 = m0, mt1 = m1;
        #pragma unroll
        for (int nb = 0; nb < 8; nb++) {
            mt0 = fmaxf(mt0, fmaxf(sfr[nb][0], sfr[nb][1]));
            mt1 = fmaxf(mt1, fmaxf(sfr[nb][2], sfr[nb][3]));
        }
        mt0 = fmaxf(mt0, __shfl_xor_sync(0xffffffff, mt0, 1));
        mt0 = fmaxf(mt0, __shfl_xor_sync(0xffffffff, mt0, 2));
        mt1 = fmaxf(mt1, __shfl_xor_sync(0xffffffff, mt1, 1));
        mt1 = fmaxf(mt1, __shfl_xor_sync(0xffffffff, mt1, 2));

        float c0 = __expf(m0 - mt0);
        float c1 = __expf(m1 - mt1);
        m0 = mt0; m1 = mt1;
        l0 *= c0; l1 *= c1;
        #pragma unroll
        for (int nb = 0; nb < 8; nb++) {
            o[nb][0] *= c0; o[nb][1] *= c0;
            o[nb][2] *= c1; o[nb][3] *= c1;
        }

        // ---- P = exp(S - m) -> tf32 into Ps (own warp rows only) ----
        #pragma unroll
        for (int nb = 0; nb < 8; nb++) {
            float p0 = __expf(sfr[nb][0] - m0);
            float p1 = __expf(sfr[nb][1] - m0);
            float p2 = __expf(sfr[nb][2] - m1);
            float p3 = __expf(sfr[nb][3] - m1);
            l0 += p0 + p1;
            l1 += p2 + p3;
            float2 w0, w1;
            w0.x = __uint_as_float(cvt_tf32(p0));
            w0.y = __uint_as_float(cvt_tf32(p1));
            w1.x = __uint_as_float(cvt_tf32(p2));
            w1.y = __uint_as_float(cvt_tf32(p3));
            *(float2*)&Ps[wid * 16 + qr]    [nb * 8 + 2 * qc] = w0;
            *(float2*)&Ps[wid * 16 + qr + 8][nb * 8 + 2 * qc] = w1;
        }
        __syncwarp();

        // ---- O += P V ----
        #pragma unroll
        for (int kk = 0; kk < 8; kk++) {
            uint32_t a0 = __float_as_uint(Ps[wid * 16 + qr]    [kk * 8 + qc]);
            uint32_t a1 = __float_as_uint(Ps[wid * 16 + qr + 8][kk * 8 + qc]);
            uint32_t a2 = __float_as_uint(Ps[wid * 16 + qr]    [kk * 8 + qc + 4]);
            uint32_t a3 = __float_as_uint(Ps[wid * 16 + qr + 8][kk * 8 + qc + 4]);
            #pragma unroll
            for (int nb = 0; nb < 8; nb++) {
                uint32_t b0 = __float_as_uint(Vs[kk * 8 + qc]    [nb * 8 + qr]);
                uint32_t b1 = __float_as_uint(Vs[kk * 8 + qc + 4][nb * 8 + qr]);
                mma_tf32(o[nb][0], o[nb][1], o[nb][2], o[nb][3],
                         a0, a1, a2, a3, b0, b1);
            }
        }
        __syncthreads();   // Ks/Vs reads done before next tile overwrite
    }

    // ---- finalize ----
    l0 += __shfl_xor_sync(0xffffffff, l0, 1);
    l0 += __shfl_xor_sync(0xffffffff, l0, 2);
    l1 += __shfl_xor_sync(0xffffffff, l1, 1);
    l1 += __shfl_xor_sync(0xffffffff, l1, 2);
    float inv0 = 1.f / l0;
    float inv1 = 1.f / l1;

    int row0 = q0 + wid * 16 + qr;
    #pragma unroll
    for (int nb = 0; nb < 8; nb++) {
        int col = h * HD + nb * 8 + 2 * qc;
        float2 w0, w1;
        w0.x = o[nb][0] * inv0; w0.y = o[nb][1] * inv0;
        w1.x = o[nb][2] * inv1; w1.y = o[nb][3] * inv1;
        *(float2*)&g_attn[(size_t)row0 * DIM + col] = w0;
        *(float2*)&g_attn[(size_t)(row0 + 8) * DIM + col] = w1;
    }
}

#define ATT_SMEM ((2 * ATT_BK * KST + ATT_BQ * KST) * 4)

// ---------------- launch ----------------
extern "C" void kernel_launch(void* const* d_in, const int* in_sizes, int n_in,
                              void* d_out, int out_size)
{
    const float* x      = (const float*)d_in[0];
    const float* cosb   = (const float*)d_in[1];
    const float* sinb   = (const float*)d_in[2];
    const float* w_qkv  = (const float*)d_in[3];
    const float* b_qkv  = (const float*)d_in[4];
    const float* w_proj = (const float*)d_in[5];
    const float* b_proj = (const float*)d_in[6];
    float* out = (float*)d_out;

    float *p_qkv, *p_attn;
    cudaGetSymbolAddress((void**)&p_qkv, g_qkv);
    cudaGetSymbolAddress((void**)&p_attn, g_attn);

    cudaFuncSetAttribute(attn_mma_kernel,
                         cudaFuncAttributeMaxDynamicSharedMemorySize, ATT_SMEM);

    // 1) QKV GEMM (tf32 MMA)
    {
        dim3 grid(QKV_N / GBN, NTOK / GBM);
        gemm_tf32_kernel<<<grid, 256>>>(x, w_qkv, b_qkv, p_qkv, NTOK, QKV_N, DIM);
    }
    // 2) RoPE + split
    {
        int total = NTOK * NHEADS * 32;
        rope_split_kernel<<<(total + 255) / 256, 256>>>(cosb, sinb);
    }
    // 3) attention (tensor-core tf32)
    {
        dim3 grid(NTOK / ATT_BQ, NHEADS);
        attn_mma_kernel<<<grid, 256, ATT_SMEM>>>();
    }
    // 4) proj GEMM (tf32 MMA)
    {
        dim3 grid(DIM / GBN, NTOK / GBM);
        gemm_tf32_kernel<<<grid, 256>>>(p_attn, w_proj, b_proj, out, NTOK, DIM, DIM);
    }
}

// round 8
// speedup vs baseline: 3.8646x; 1.0241x over previous
#include <cuda_runtime.h>
#include <stdint.h>
#include <math.h>

#define NTOK 4096
#define DIM 1024
#define NHEADS 16
#define HD 64
#define QKV_N 3072
#define SCALE 0.125f   // 1/sqrt(64)

// ---------------- scratch (no allocations allowed) ----------------
__device__ float g_qkv[NTOK * QKV_N];
__device__ float g_Q[NHEADS * NTOK * HD];
__device__ float g_K[NHEADS * NTOK * HD];
__device__ float g_V[NHEADS * NTOK * HD];
__device__ float g_attn[NTOK * DIM];

__device__ __forceinline__ uint32_t cvt_tf32(float x) {
    uint32_t r;
    asm("cvt.rna.tf32.f32 %0, %1;" : "=r"(r) : "f"(x));
    return r;
}

__device__ __forceinline__ void mma_tf32(float& c0, float& c1, float& c2, float& c3,
                                         uint32_t a0, uint32_t a1, uint32_t a2, uint32_t a3,
                                         uint32_t b0, uint32_t b1) {
    asm volatile(
        "mma.sync.aligned.m16n8k8.row.col.f32.tf32.tf32.f32 "
        "{%0,%1,%2,%3}, {%4,%5,%6,%7}, {%8,%9}, {%0,%1,%2,%3};"
        : "+f"(c0), "+f"(c1), "+f"(c2), "+f"(c3)
        : "r"(a0), "r"(a1), "r"(a2), "r"(a3), "r"(b0), "r"(b1));
}

// ---------------- tf32 MMA GEMM with register-prefetch pipeline ----------------
// 128x128 CTA tile, BK=16, 256 threads = 8 warps in 2(m) x 4(n), warp tile 64x32.
#define GBM 128
#define GBN 128
#define GBK 16
#define GST 136   // smem row stride: 136 mod 32 = 8 -> conflict-free frags

__global__ __launch_bounds__(256, 2) void gemm_tf32_kernel(
    const float* __restrict__ A, const float* __restrict__ B,
    const float* __restrict__ bias, float* __restrict__ C,
    int M, int N, int K)
{
    __shared__ float Ast[GBK][GST];   // A^T tile: [k][m], tf32 bits
    __shared__ float Bs[GBK][GST];    // B tile:  [k][n], tf32 bits

    const int tid = threadIdx.x;
    const int wid = tid >> 5;
    const int lane = tid & 31;
    const int qr = lane >> 2;
    const int qc = lane & 3;
    const int wm = wid >> 2;
    const int wn = wid & 3;
    const int rowBase = blockIdx.y * GBM;
    const int colBase = blockIdx.x * GBN;

    // per-thread load coordinates (2 float4 each for A and B)
    int ar[2], ac[2], br[2], bc[2];
    #pragma unroll
    for (int i = 0; i < 2; i++) {
        int v = tid + i * 256;
        ar[i] = v >> 2;  ac[i] = (v & 3) * 4;
        br[i] = v >> 5;  bc[i] = (v & 31) * 4;
    }

    float acc[4][4][4];
    #pragma unroll
    for (int mi = 0; mi < 4; mi++)
        #pragma unroll
        for (int ni = 0; ni < 4; ni++)
            #pragma unroll
            for (int r = 0; r < 4; r++) acc[mi][ni][r] = 0.f;

    // prefetch tile 0
    float4 pa[2], pb[2];
    #pragma unroll
    for (int i = 0; i < 2; i++) {
        pa[i] = *(const float4*)&A[(size_t)(rowBase + ar[i]) * K + ac[i]];
        pb[i] = *(const float4*)&B[(size_t)br[i] * N + colBase + bc[i]];
    }

    for (int k0 = 0; k0 < K; k0 += GBK) {
        // store prefetched tile to smem (tf32 bits)
        #pragma unroll
        for (int i = 0; i < 2; i++) {
            Ast[ac[i] + 0][ar[i]] = __uint_as_float(cvt_tf32(pa[i].x));
            Ast[ac[i] + 1][ar[i]] = __uint_as_float(cvt_tf32(pa[i].y));
            Ast[ac[i] + 2][ar[i]] = __uint_as_float(cvt_tf32(pa[i].z));
            Ast[ac[i] + 3][ar[i]] = __uint_as_float(cvt_tf32(pa[i].w));
            float4 g;
            g.x = __uint_as_float(cvt_tf32(pb[i].x));
            g.y = __uint_as_float(cvt_tf32(pb[i].y));
            g.z = __uint_as_float(cvt_tf32(pb[i].z));
            g.w = __uint_as_float(cvt_tf32(pb[i].w));
            *(float4*)&Bs[br[i]][bc[i]] = g;
        }
        __syncthreads();

        // issue next tile's global loads early (hidden behind MMAs)
        if (k0 + GBK < K) {
            #pragma unroll
            for (int i = 0; i < 2; i++) {
                pa[i] = *(const float4*)&A[(size_t)(rowBase + ar[i]) * K + (k0 + GBK) + ac[i]];
                pb[i] = *(const float4*)&B[(size_t)(k0 + GBK + br[i]) * N + colBase + bc[i]];
            }
        }

        #pragma unroll
        for (int kk = 0; kk < 2; kk++) {
            uint32_t af[4][4], bf[4][2];
            #pragma unroll
            for (int mi = 0; mi < 4; mi++) {
                int m = wm * 64 + mi * 16;
                af[mi][0] = __float_as_uint(Ast[kk * 8 + qc]    [m + qr]);
                af[mi][1] = __float_as_uint(Ast[kk * 8 + qc]    [m + qr + 8]);
                af[mi][2] = __float_as_uint(Ast[kk * 8 + qc + 4][m + qr]);
                af[mi][3] = __float_as_uint(Ast[kk * 8 + qc + 4][m + qr + 8]);
            }
            #pragma unroll
            for (int ni = 0; ni < 4; ni++) {
                int n = wn * 32 + ni * 8;
                bf[ni][0] = __float_as_uint(Bs[kk * 8 + qc]    [n + qr]);
                bf[ni][1] = __float_as_uint(Bs[kk * 8 + qc + 4][n + qr]);
            }
            #pragma unroll
            for (int mi = 0; mi < 4; mi++)
                #pragma unroll
                for (int ni = 0; ni < 4; ni++)
                    mma_tf32(acc[mi][ni][0], acc[mi][ni][1], acc[mi][ni][2], acc[mi][ni][3],
                             af[mi][0], af[mi][1], af[mi][2], af[mi][3],
                             bf[ni][0], bf[ni][1]);
        }
        __syncthreads();
    }

    #pragma unroll
    for (int mi = 0; mi < 4; mi++) {
        int m = rowBase + wm * 64 + mi * 16;
        #pragma unroll
        for (int ni = 0; ni < 4; ni++) {
            int n = colBase + wn * 32 + ni * 8 + 2 * qc;
            float bx = bias[n], by = bias[n + 1];
            float2 w0, w1;
            w0.x = acc[mi][ni][0] + bx;  w0.y = acc[mi][ni][1] + by;
            w1.x = acc[mi][ni][2] + bx;  w1.y = acc[mi][ni][3] + by;
            *(float2*)&C[(size_t)(m + qr) * N + n] = w0;
            *(float2*)&C[(size_t)(m + qr + 8) * N + n] = w1;
        }
    }
}

// ---------------- RoPE + split qkv -> Q/K/V in [h][n][hd] ----------------
__global__ void rope_split_kernel(const float* __restrict__ cosb,
                                  const float* __restrict__ sinb)
{
    int idx = blockIdx.x * blockDim.x + threadIdx.x;
    if (idx >= NTOK * NHEADS * 32) return;
    int d = idx & 31;
    int h = (idx >> 5) & 15;
    int n = idx >> 9;

    const float* base = g_qkv + (size_t)n * QKV_N;
    float c = cosb[n * 32 + d];
    float s = sinb[n * 32 + d];

    size_t ho = ((size_t)h * NTOK + n) * HD;

    float x1 = base[h * HD + d];
    float x2 = base[h * HD + d + 32];
    g_Q[ho + d]      = x1 * c - x2 * s;
    g_Q[ho + d + 32] = x2 * c + x1 * s;

    float y1 = base[DIM + h * HD + d];
    float y2 = base[DIM + h * HD + d + 32];
    g_K[ho + d]      = y1 * c - y2 * s;
    g_K[ho + d + 32] = y2 * c + y1 * s;

    g_V[ho + d]      = base[2 * DIM + h * HD + d];
    g_V[ho + d + 32] = base[2 * DIM + h * HD + d + 32];
}

// ---------------- flash attention with mma.sync tf32 ----------------
// CTA: 128 queries x 1 head, 8 warps. Target 2 CTAs/SM for latency hiding.
#define ATT_BQ 128
#define ATT_BK 64
#define KST 68    // padded row stride (floats)

__global__ __launch_bounds__(256, 2) void attn_mma_kernel()
{
    extern __shared__ float sm[];
    float (*Ks)[KST] = (float(*)[KST])sm;                       // [64][68]
    float (*Vs)[KST] = (float(*)[KST])(sm + ATT_BK * KST);      // [64][68]
    float (*Ps)[KST] = (float(*)[KST])(sm + 2 * ATT_BK * KST);  // [128][68]

    const int h = blockIdx.y;
    const int q0 = blockIdx.x * ATT_BQ;
    const int wid = threadIdx.x >> 5;
    const int lane = threadIdx.x & 31;
    const int qr = lane >> 2;
    const int qc = lane & 3;

    const float* qbase = g_Q + ((size_t)h * NTOK + q0 + wid * 16) * HD;
    uint32_t qf[8][4];
    #pragma unroll
    for (int kk = 0; kk < 8; kk++) {
        qf[kk][0] = cvt_tf32(qbase[(size_t)(qr)     * HD + kk * 8 + qc]     * SCALE);
        qf[kk][1] = cvt_tf32(qbase[(size_t)(qr + 8) * HD + kk * 8 + qc]     * SCALE);
        qf[kk][2] = cvt_tf32(qbase[(size_t)(qr)     * HD + kk * 8 + qc + 4] * SCALE);
        qf[kk][3] = cvt_tf32(qbase[(size_t)(qr + 8) * HD + kk * 8 + qc + 4] * SCALE);
    }

    float m0 = -1e30f, m1 = -1e30f, l0 = 0.f, l1 = 0.f;
    float o[8][4];
    #pragma unroll
    for (int nb = 0; nb < 8; nb++)
        #pragma unroll
        for (int r = 0; r < 4; r++) o[nb][r] = 0.f;

    const float* kb = g_K + (size_t)h * NTOK * HD;
    const float* vb = g_V + (size_t)h * NTOK * HD;

    #pragma unroll 1
    for (int t = 0; t < NTOK; t += ATT_BK) {
        #pragma unroll
        for (int i = 0; i < 4; i++) {
            int v = threadIdx.x + i * 256;
            int r = v >> 4;
            int c = (v & 15) * 4;
            float4 fk = *(const float4*)&kb[(size_t)(t + r) * HD + c];
            float4 fv = *(const float4*)&vb[(size_t)(t + r) * HD + c];
            float4 gk, gv;
            gk.x = __uint_as_float(cvt_tf32(fk.x)); gk.y = __uint_as_float(cvt_tf32(fk.y));
            gk.z = __uint_as_float(cvt_tf32(fk.z)); gk.w = __uint_as_float(cvt_tf32(fk.w));
            gv.x = __uint_as_float(cvt_tf32(fv.x)); gv.y = __uint_as_float(cvt_tf32(fv.y));
            gv.z = __uint_as_float(cvt_tf32(fv.z)); gv.w = __uint_as_float(cvt_tf32(fv.w));
            *(float4*)&Ks[r][c] = gk;
            *(float4*)&Vs[r][c] = gv;
        }
        __syncthreads();

        float sfr[8][4];
        #pragma unroll
        for (int nb = 0; nb < 8; nb++)
            #pragma unroll
            for (int r = 0; r < 4; r++) sfr[nb][r] = 0.f;

        #pragma unroll
        for (int kk = 0; kk < 8; kk++) {
            #pragma unroll
            for (int nb = 0; nb < 8; nb++) {
                uint32_t b0 = __float_as_uint(Ks[nb * 8 + qr][kk * 8 + qc]);
                uint32_t b1 = __float_as_uint(Ks[nb * 8 + qr][kk * 8 + qc + 4]);
                mma_tf32(sfr[nb][0], sfr[nb][1], sfr[nb][2], sfr[nb][3],
                         qf[kk][0], qf[kk][1], qf[kk][2], qf[kk][3], b0, b1);
            }
        }

        float mt0 = m0, mt1 = m1;
        #pragma unroll
        for (int nb = 0; nb < 8; nb++) {
            mt0 = fmaxf(mt0, fmaxf(sfr[nb][0], sfr[nb][1]));
            mt1 = fmaxf(mt1, fmaxf(sfr[nb][2], sfr[nb][3]));
        }
        mt0 = fmaxf(mt0, __shfl_xor_sync(0xffffffff, mt0, 1));
        mt0 = fmaxf(mt0, __shfl_xor_sync(0xffffffff, mt0, 2));
        mt1 = fmaxf(mt1, __shfl_xor_sync(0xffffffff, mt1, 1));
        mt1 = fmaxf(mt1, __shfl_xor_sync(0xffffffff, mt1, 2));

        float c0 = __expf(m0 - mt0);
        float c1 = __expf(m1 - mt1);
        m0 = mt0; m1 = mt1;
        l0 *= c0; l1 *= c1;
        #pragma unroll
        for (int nb = 0; nb < 8; nb++) {
            o[nb][0] *= c0; o[nb][1] *= c0;
            o[nb][2] *= c1; o[nb][3] *= c1;
        }

        #pragma unroll
        for (int nb = 0; nb < 8; nb++) {
            float p0 = __expf(sfr[nb][0] - m0);
            float p1 = __expf(sfr[nb][1] - m0);
            float p2 = __expf(sfr[nb][2] - m1);
            float p3 = __expf(sfr[nb][3] - m1);
            l0 += p0 + p1;
            l1 += p2 + p3;
            float2 w0, w1;
            w0.x = __uint_as_float(cvt_tf32(p0));
            w0.y = __uint_as_float(cvt_tf32(p1));
            w1.x = __uint_as_float(cvt_tf32(p2));
            w1.y = __uint_as_float(cvt_tf32(p3));
            *(float2*)&Ps[wid * 16 + qr]    [nb * 8 + 2 * qc] = w0;
            *(float2*)&Ps[wid * 16 + qr + 8][nb * 8 + 2 * qc] = w1;
        }
        __syncwarp();

        #pragma unroll
        for (int kk = 0; kk < 8; kk++) {
            uint32_t a0 = __float_as_uint(Ps[wid * 16 + qr]    [kk * 8 + qc]);
            uint32_t a1 = __float_as_uint(Ps[wid * 16 + qr + 8][kk * 8 + qc]);
            uint32_t a2 = __float_as_uint(Ps[wid * 16 + qr]    [kk * 8 + qc + 4]);
            uint32_t a3 = __float_as_uint(Ps[wid * 16 + qr + 8][kk * 8 + qc + 4]);
            #pragma unroll
            for (int nb = 0; nb < 8; nb++) {
                uint32_t b0 = __float_as_uint(Vs[kk * 8 + qc]    [nb * 8 + qr]);
                uint32_t b1 = __float_as_uint(Vs[kk * 8 + qc + 4][nb * 8 + qr]);
                mma_tf32(o[nb][0], o[nb][1], o[nb][2], o[nb][3],
                         a0, a1, a2, a3, b0, b1);
            }
        }
        __syncthreads();
    }

    l0 += __shfl_xor_sync(0xffffffff, l0, 1);
    l0 += __shfl_xor_sync(0xffffffff, l0, 2);
    l1 += __shfl_xor_sync(0xffffffff, l1, 1);
    l1 += __shfl_xor_sync(0xffffffff, l1, 2);
    float inv0 = 1.f / l0;
    float inv1 = 1.f / l1;

    int row0 = q0 + wid * 16 + qr;
    #pragma unroll
    for (int nb = 0; nb < 8; nb++) {
        int col = h * HD + nb * 8 + 2 * qc;
        float2 w0, w1;
        w0.x = o[nb][0] * inv0; w0.y = o[nb][1] * inv0;
        w1.x = o[nb][2] * inv1; w1.y = o[nb][3] * inv1;
        *(float2*)&g_attn[(size_t)row0 * DIM + col] = w0;
        *(float2*)&g_attn[(size_t)(row0 + 8) * DIM + col] = w1;
    }
}

#define ATT_SMEM ((2 * ATT_BK * KST + ATT_BQ * KST) * 4)

// ---------------- launch ----------------
extern "C" void kernel_launch(void* const* d_in, const int* in_sizes, int n_in,
                              void* d_out, int out_size)
{
    const float* x      = (const float*)d_in[0];
    const float* cosb   = (const float*)d_in[1];
    const float* sinb   = (const float*)d_in[2];
    const float* w_qkv  = (const float*)d_in[3];
    const float* b_qkv  = (const float*)d_in[4];
    const float* w_proj = (const float*)d_in[5];
    const float* b_proj = (const float*)d_in[6];
    float* out = (float*)d_out;

    float *p_qkv, *p_attn;
    cudaGetSymbolAddress((void**)&p_qkv, g_qkv);
    cudaGetSymbolAddress((void**)&p_attn, g_attn);

    cudaFuncSetAttribute(attn_mma_kernel,
                         cudaFuncAttributeMaxDynamicSharedMemorySize, ATT_SMEM);

    // 1) QKV GEMM (tf32 MMA, prefetch-pipelined)
    {
        dim3 grid(QKV_N / GBN, NTOK / GBM);
        gemm_tf32_kernel<<<grid, 256>>>(x, w_qkv, b_qkv, p_qkv, NTOK, QKV_N, DIM);
    }
    // 2) RoPE + split
    {
        int total = NTOK * NHEADS * 32;
        rope_split_kernel<<<(total + 255) / 256, 256>>>(cosb, sinb);
    }
    // 3) attention (tensor-core tf32, 2 CTAs/SM)
    {
        dim3 grid(NTOK / ATT_BQ, NHEADS);
        attn_mma_kernel<<<grid, 256, ATT_SMEM>>>();
    }
    // 4) proj GEMM (tf32 MMA)
    {
        dim3 grid(DIM / GBN, NTOK / GBM);
        gemm_tf32_kernel<<<grid, 256>>>(p_attn, w_proj, b_proj, out, NTOK, DIM, DIM);
    }
}